// round 14
// baseline (speedup 1.0000x reference)
#include <cuda_runtime.h>
#include <cuda_bf16.h>
#include <math.h>

#define N_NODES 50000
#define N_EDGES 800000
#define N_GRAPHS 256
#define D_HID 256
#define SCAN_B 1024
#define N_SCANBLK ((N_NODES + SCAN_B - 1) / SCAN_B)   // 49

// ---------------- scratch (device globals; all self-restoring) ---------------
__device__ float g_dinv[N_NODES];
__device__ int   g_deg[N_NODES];                       // restored by scan_one
__device__ int   g_rowptr[N_NODES + 1];
__device__ int   g_cursor[N_NODES];
__device__ int   g_colidx[N_EDGES];
__device__ unsigned long long g_scanstate[N_SCANBLK];  // restored by fill
__device__ int   g_ticket;                             // restored by fill
__device__ float g_xs[(size_t)N_NODES * 16];           // dinv[n]*x[n], padded to 16
__device__ __nv_bfloat16 g_h1[(size_t)N_NODES * D_HID];
__device__ __nv_bfloat16 g_agg[(size_t)N_NODES * D_HID];
__device__ float g_pool[N_GRAPHS * D_HID];             // restored by head
__device__ int   g_cnt[N_GRAPHS];                      // restored by head
__device__ int   g_is32_ei;
__device__ int   g_is32_batch;

__device__ __forceinline__ float selu_f(float v) {
    const float a = 1.6732632423543772f, s = 1.0507009873554805f;
    return v > 0.f ? s * v : s * a * (expf(v) - 1.f);
}

__device__ __forceinline__ int load_idx(const void* p, long long i, int is32) {
    if (is32) return ((const int*)p)[i];
    return (int)((const long long*)p)[i];
}

__device__ __forceinline__ unsigned f2tf32(float f) {
    unsigned r;
    asm("cvt.rna.tf32.f32 %0, %1;" : "=r"(r) : "f"(f));
    return r;
}

// ------ deg/cnt histograms with per-block dtype sniff (no init kernel) -------
__global__ void deg_count_kernel(const void* __restrict__ ei, const void* __restrict__ batch) {
    __shared__ int s_ei, s_b;
    int t = threadIdx.x;
    if (t < 32) {
        int v = ((const int*)ei)[2 * (t * 256) + 1];
        unsigned m = __ballot_sync(0xffffffffu, v != 0);
        int w = ((const int*)batch)[2 * (t * 256) + 1];
        unsigned m2 = __ballot_sync(0xffffffffu, w != 0);
        if (t == 0) { s_ei = (m != 0); s_b = (m2 != 0); }
    }
    __syncthreads();
    int is32e = s_ei, is32b = s_b;
    int i = blockIdx.x * blockDim.x + t;
    if (i == 0) { g_is32_ei = is32e; g_is32_batch = is32b; }
    if (i < N_EDGES) atomicAdd(&g_deg[load_idx(ei, (long long)N_EDGES + i, is32e)], 1);
    if (i < N_NODES) atomicAdd(&g_cnt[load_idx(batch, i, is32b)], 1);
}

// ------- single-kernel decoupled-lookback scan (+cursor+dinv, deg restore) ---
__global__ void __launch_bounds__(SCAN_B) scan_one() {
    __shared__ int warp_sums[32];
    __shared__ int s_bid, s_exc;
    int t = threadIdx.x;
    if (t == 0) s_bid = atomicAdd(&g_ticket, 1);
    __syncthreads();
    int b = s_bid;
    int i = b * SCAN_B + t;
    int v = (i < N_NODES) ? g_deg[i] : 0;
    int x = v;
    #pragma unroll
    for (int off = 1; off < 32; off <<= 1) {
        int y = __shfl_up_sync(0xffffffffu, x, off);
        if ((t & 31) >= off) x += y;
    }
    if ((t & 31) == 31) warp_sums[t >> 5] = x;
    __syncthreads();
    if (t < 32) {
        int s = warp_sums[t];
        #pragma unroll
        for (int off = 1; off < 32; off <<= 1) {
            int y = __shfl_up_sync(0xffffffffu, s, off);
            if (t >= off) s += y;
        }
        warp_sums[t] = s;
    }
    __syncthreads();
    int inc = x + ((t >= 32) ? warp_sums[(t >> 5) - 1] : 0);

    if (t == 0) {
        int total = warp_sums[31];
        if (b == 0) {
            atomicExch(&g_scanstate[0], (2ULL << 32) | (unsigned)total);
            s_exc = 0;
        } else {
            atomicExch(&g_scanstate[b], (1ULL << 32) | (unsigned)total);
            int exc = 0;
            int j = b - 1;
            while (true) {
                unsigned long long st;
                do { st = atomicAdd(&g_scanstate[j], 0ULL); } while ((st >> 32) == 0ULL);
                exc += (int)(unsigned)st;
                if ((st >> 32) == 2ULL) break;
                j--;
            }
            atomicExch(&g_scanstate[b], (2ULL << 32) | (unsigned)(total + exc));
            s_exc = exc;
        }
    }
    __syncthreads();
    int exc = s_exc;
    int r = exc + inc - v;   // exclusive prefix
    if (i < N_NODES) {
        g_rowptr[i] = r;
        g_cursor[i] = r;
        g_dinv[i] = rsqrtf((float)(v + 1));
        g_deg[i] = 0;                       // restore for next run
    }
    if (i == N_NODES - 1) g_rowptr[N_NODES] = exc + inc;
}

// fill colidx + xs precompute (dinv ready) + scan-state restore
__global__ void fill_kernel(const void* __restrict__ ei, const float* __restrict__ x) {
    int i = blockIdx.x * blockDim.x + threadIdx.x;
    int is32 = g_is32_ei;
    if (i < N_EDGES) {
        int d = load_idx(ei, (long long)N_EDGES + i, is32);
        int p = atomicAdd(&g_cursor[d], 1);
        g_colidx[p] = load_idx(ei, i, is32);
    }
    if (i < N_NODES) {
        float di = g_dinv[i];
        float buf[16];
        #pragma unroll
        for (int f = 0; f < 14; f++) buf[f] = di * x[(size_t)i * 14 + f];
        buf[14] = 0.f; buf[15] = 0.f;
        float4* o = (float4*)(g_xs + (size_t)i * 16);
        o[0] = *(float4*)&buf[0];
        o[1] = *(float4*)&buf[4];
        o[2] = *(float4*)&buf[8];
        o[3] = *(float4*)&buf[12];
    }
    if (i < N_SCANBLK) g_scanstate[i] = 0ULL;   // restore (scan_one fully done)
    if (i == N_SCANBLK) g_ticket = 0;           // restore
}

// ------- layer 1 fused: float4 gather of xs (8 edges/iter/warp), then GEMM ---
__global__ void gemm1_fused(const float* __restrict__ W1, const float* __restrict__ b1) {
    __shared__ __align__(16) float sx[32][16];
    int row0 = blockIdx.x * 32;
    int tid = threadIdx.x;  // 256
    int warp = tid >> 5, lane = tid & 31;
    int slot = lane >> 2;   // 0..7 edge slot
    int q = lane & 3;       // quad within xs row
    const float4* xs4 = (const float4*)g_xs;

    // phase 1: each warp aggregates 4 rows; all 32 lanes active, no divergence
    #pragma unroll
    for (int rr = 0; rr < 4; rr++) {
        int r = warp * 4 + rr;
        int row = row0 + r;
        float4 acc = make_float4(0.f, 0.f, 0.f, 0.f);
        float di = 0.f;
        if (row < N_NODES) {
            di = g_dinv[row];
            if (slot == 0) acc = xs4[(size_t)row * 4 + q];   // self term
            int e0 = g_rowptr[row], e1 = g_rowptr[row + 1];
            for (int e = e0; e < e1; e += 8) {
                int ee = e + slot;
                if (ee < e1) {
                    int s = g_colidx[ee];
                    float4 v = xs4[(size_t)s * 4 + q];
                    acc.x += v.x; acc.y += v.y; acc.z += v.z; acc.w += v.w;
                }
            }
        }
        // reduce over the 8 slots (lane bits 2..4 -> xor offsets 4,8,16)
        #pragma unroll
        for (int off = 4; off < 32; off <<= 1) {
            acc.x += __shfl_xor_sync(0xffffffffu, acc.x, off);
            acc.y += __shfl_xor_sync(0xffffffffu, acc.y, off);
            acc.z += __shfl_xor_sync(0xffffffffu, acc.z, off);
            acc.w += __shfl_xor_sync(0xffffffffu, acc.w, off);
        }
        if (slot == 0) {
            float4 o = make_float4(di * acc.x, di * acc.y, di * acc.z, di * acc.w);
            *(float4*)&sx[r][q * 4] = o;
        }
    }
    __syncthreads();

    // phase 2: [32,14] @ [14,256] + bias + selu -> bf16 h1
    float w[14];
    #pragma unroll
    for (int k = 0; k < 14; k++) w[k] = W1[k * 256 + tid];
    float bj = b1[tid];
    for (int r = 0; r < 32; r++) {
        int row = row0 + r;
        if (row >= N_NODES) break;
        float acc = bj;
        #pragma unroll
        for (int k = 0; k < 14; k++) acc += sx[r][k] * w[k];
        g_h1[(size_t)row * 256 + tid] = __float2bfloat16(selu_f(acc));
    }
}

// ------- layer 2 aggregate: bf16 gather, unroll 8/4/1 ladder -----------------
__global__ void agg2_kernel() {
    int w = (blockIdx.x * blockDim.x + threadIdx.x) >> 5;
    int lane = threadIdx.x & 31;
    if (w >= N_NODES) return;
    float di = g_dinv[w];
    float acc[8];
    {
        float4 raw = ((const float4*)(g_h1 + (size_t)w * 256))[lane];
        const __nv_bfloat162* p = (const __nv_bfloat162*)&raw;
        #pragma unroll
        for (int q = 0; q < 4; q++) {
            float2 v = __bfloat1622float2(p[q]);
            acc[2 * q]     = di * v.x;
            acc[2 * q + 1] = di * v.y;
        }
    }
    int e0 = g_rowptr[w], e1 = g_rowptr[w + 1];
    int e = e0;
    for (; e + 8 <= e1; e += 8) {
        int s[8];
        float ds[8];
        float4 raw[8];
        #pragma unroll
        for (int u = 0; u < 8; u++) s[u] = g_colidx[e + u];
        #pragma unroll
        for (int u = 0; u < 8; u++) ds[u] = g_dinv[s[u]];
        #pragma unroll
        for (int u = 0; u < 8; u++)
            raw[u] = ((const float4*)(g_h1 + (size_t)s[u] * 256))[lane];
        #pragma unroll
        for (int u = 0; u < 8; u++) {
            const __nv_bfloat162* p = (const __nv_bfloat162*)&raw[u];
            #pragma unroll
            for (int q = 0; q < 4; q++) {
                float2 v = __bfloat1622float2(p[q]);
                acc[2 * q]     += ds[u] * v.x;
                acc[2 * q + 1] += ds[u] * v.y;
            }
        }
    }
    for (; e + 4 <= e1; e += 4) {
        int s[4];
        float ds[4];
        float4 raw[4];
        #pragma unroll
        for (int u = 0; u < 4; u++) s[u] = g_colidx[e + u];
        #pragma unroll
        for (int u = 0; u < 4; u++) ds[u] = g_dinv[s[u]];
        #pragma unroll
        for (int u = 0; u < 4; u++)
            raw[u] = ((const float4*)(g_h1 + (size_t)s[u] * 256))[lane];
        #pragma unroll
        for (int u = 0; u < 4; u++) {
            const __nv_bfloat162* p = (const __nv_bfloat162*)&raw[u];
            #pragma unroll
            for (int q = 0; q < 4; q++) {
                float2 v = __bfloat1622float2(p[q]);
                acc[2 * q]     += ds[u] * v.x;
                acc[2 * q + 1] += ds[u] * v.y;
            }
        }
    }
    for (; e < e1; e++) {
        int s = g_colidx[e];
        float ds = g_dinv[s];
        float4 raw = ((const float4*)(g_h1 + (size_t)s * 256))[lane];
        const __nv_bfloat162* p = (const __nv_bfloat162*)&raw;
        #pragma unroll
        for (int q = 0; q < 4; q++) {
            float2 v = __bfloat1622float2(p[q]);
            acc[2 * q]     += ds * v.x;
            acc[2 * q + 1] += ds * v.y;
        }
    }
    __nv_bfloat162 h[4];
    #pragma unroll
    for (int q = 0; q < 4; q++)
        h[q] = __floats2bfloat162_rn(di * acc[2 * q], di * acc[2 * q + 1]);
    ((float4*)(g_agg + (size_t)w * 256))[lane] = *(float4*)h;
}

// ---------------- GEMM2 (tf32 TC, bf16 A) with fused bias+selu+pool ----------
#define GM 128
#define GN 128
#define GK 32
#define GS (GM + 4)

__global__ void __launch_bounds__(256, 2) gemm2_tc(const float* __restrict__ W,
                                                   const float* __restrict__ bias,
                                                   const void* __restrict__ batch) {
    __shared__ unsigned As[GK][GS];
    __shared__ unsigned Bs[GK][GS];
    int m0 = blockIdx.x * GM, n0 = blockIdx.y * GN;
    int tid = threadIdx.x;
    int lane = tid & 31, warp = tid >> 5;
    int wm = (warp >> 1) * 32;
    int wn = (warp & 1) * 64;
    int g = lane >> 2, tg = lane & 3;

    float d[2][8][4];
    #pragma unroll
    for (int mi = 0; mi < 2; mi++)
        #pragma unroll
        for (int ni = 0; ni < 8; ni++)
            #pragma unroll
            for (int q = 0; q < 4; q++) d[mi][ni][q] = 0.f;

    for (int k0 = 0; k0 < 256; k0 += GK) {
        #pragma unroll
        for (int it = 0; it < 2; it++) {
            int idx = tid + it * 256;
            int row = idx >> 2;
            int c = (idx & 3) * 8;
            float4 raw = make_float4(0.f, 0.f, 0.f, 0.f);
            if (m0 + row < N_NODES)
                raw = *(const float4*)(g_agg + (size_t)(m0 + row) * 256 + k0 + c);
            const __nv_bfloat162* p = (const __nv_bfloat162*)&raw;
            #pragma unroll
            for (int q = 0; q < 4; q++) {
                float2 v = __bfloat1622float2(p[q]);
                As[c + 2 * q][row]     = f2tf32(v.x);
                As[c + 2 * q + 1][row] = f2tf32(v.y);
            }
        }
        #pragma unroll
        for (int it = 0; it < 4; it++) {
            int idx = tid + it * 256;
            int kr = idx >> 5;
            int nc = (idx & 31) * 4;
            float4 bv = *(const float4*)(W + (size_t)(k0 + kr) * 256 + n0 + nc);
            Bs[kr][nc + 0] = f2tf32(bv.x);
            Bs[kr][nc + 1] = f2tf32(bv.y);
            Bs[kr][nc + 2] = f2tf32(bv.z);
            Bs[kr][nc + 3] = f2tf32(bv.w);
        }
        __syncthreads();

        #pragma unroll
        for (int kk = 0; kk < GK; kk += 8) {
            unsigned a[2][4], b[8][2];
            #pragma unroll
            for (int mi = 0; mi < 2; mi++) {
                int mb = wm + mi * 16;
                a[mi][0] = As[kk + tg][mb + g];
                a[mi][1] = As[kk + tg][mb + g + 8];
                a[mi][2] = As[kk + tg + 4][mb + g];
                a[mi][3] = As[kk + tg + 4][mb + g + 8];
            }
            #pragma unroll
            for (int ni = 0; ni < 8; ni++) {
                int nb = wn + ni * 8;
                b[ni][0] = Bs[kk + tg][nb + g];
                b[ni][1] = Bs[kk + tg + 4][nb + g];
            }
            #pragma unroll
            for (int mi = 0; mi < 2; mi++)
                #pragma unroll
                for (int ni = 0; ni < 8; ni++)
                    asm volatile(
                        "mma.sync.aligned.m16n8k8.row.col.f32.tf32.tf32.f32 "
                        "{%0,%1,%2,%3},{%4,%5,%6,%7},{%8,%9},{%0,%1,%2,%3};"
                        : "+f"(d[mi][ni][0]), "+f"(d[mi][ni][1]),
                          "+f"(d[mi][ni][2]), "+f"(d[mi][ni][3])
                        : "r"(a[mi][0]), "r"(a[mi][1]), "r"(a[mi][2]), "r"(a[mi][3]),
                          "r"(b[ni][0]), "r"(b[ni][1]));
        }
        __syncthreads();
    }

    // ---- fused epilogue: bias + selu + segmented pool -> g_pool atomics ----
    int is32 = g_is32_batch;
    #pragma unroll
    for (int mi = 0; mi < 2; mi++) {
        int rbase = m0 + wm + mi * 16;
        int r0 = rbase + g;
        int r1 = r0 + 8;
        bool full = (rbase + 15) < N_NODES;
        int gid_first = load_idx(batch, full ? rbase : (N_NODES - 1), is32);
        int gid_last  = load_idx(batch, full ? (rbase + 15) : (N_NODES - 1), is32);
        bool uniform = full && (gid_first == gid_last);
        #pragma unroll
        for (int ni = 0; ni < 8; ni++) {
            int c0 = n0 + wn + ni * 8 + 2 * tg;
            float bz0 = bias[c0], bz1 = bias[c0 + 1];
            float v00 = selu_f(d[mi][ni][0] + bz0);
            float v01 = selu_f(d[mi][ni][1] + bz1);
            float v10 = selu_f(d[mi][ni][2] + bz0);
            float v11 = selu_f(d[mi][ni][3] + bz1);
            if (uniform) {
                float s0 = v00 + v10;
                float s1 = v01 + v11;
                #pragma unroll
                for (int off = 4; off < 32; off <<= 1) {
                    s0 += __shfl_xor_sync(0xffffffffu, s0, off);
                    s1 += __shfl_xor_sync(0xffffffffu, s1, off);
                }
                if (g == 0) {
                    atomicAdd(&g_pool[gid_first * 256 + c0], s0);
                    atomicAdd(&g_pool[gid_first * 256 + c0 + 1], s1);
                }
            } else {
                if (r0 < N_NODES) {
                    int gr = load_idx(batch, r0, is32);
                    atomicAdd(&g_pool[gr * 256 + c0], v00);
                    atomicAdd(&g_pool[gr * 256 + c0 + 1], v01);
                }
                if (r1 < N_NODES) {
                    int gr = load_idx(batch, r1, is32);
                    atomicAdd(&g_pool[gr * 256 + c0], v10);
                    atomicAdd(&g_pool[gr * 256 + c0 + 1], v11);
                }
            }
        }
    }
}

// ---------------- head (restores g_pool/g_cnt to zero) -----------------------
__global__ void head_kernel(const float* __restrict__ fc1w, const float* __restrict__ fc1b,
                            const float* __restrict__ fc2w, const float* __restrict__ fc2b,
                            float* __restrict__ out) {
    __shared__ __align__(16) float sp[256];
    __shared__ __align__(16) float sg[128];
    __shared__ float slog[2];
    int g = blockIdx.x, t = threadIdx.x;  // 128 threads
    float c = fmaxf((float)g_cnt[g], 1.0f);
    for (int j = t; j < 256; j += 128) {
        sp[j] = selu_f(g_pool[g * 256 + j] / c);
        g_pool[g * 256 + j] = 0.f;     // restore for next run
    }
    __syncthreads();
    if (t == 0) g_cnt[g] = 0;          // restore (after c read)
    float acc = fc1b[t];
    for (int k = 0; k < 256; k++) acc += sp[k] * fc1w[k * 128 + t];
    sg[t] = selu_f(acc);
    __syncthreads();
    if (t < 2) {
        float a = fc2b[t];
        for (int k = 0; k < 128; k++) a += sg[k] * fc2w[k * 2 + t];
        slog[t] = a;
    }
    __syncthreads();
    if (t < 2) {
        float m = fmaxf(slog[0], slog[1]);
        float lse = m + logf(expf(slog[0] - m) + expf(slog[1] - m));
        out[g * 2 + t] = slog[t] - lse;
    }
}

// ---------------- launch -----------------------------------------------------
extern "C" void kernel_launch(void* const* d_in, const int* in_sizes, int n_in,
                              void* d_out, int out_size) {
    const float* x     = (const float*)d_in[0];
    const void*  ei    = d_in[1];
    const void*  batch = d_in[2];
    const float* W1  = (const float*)d_in[3];
    const float* b1  = (const float*)d_in[4];
    const float* W2  = (const float*)d_in[5];
    const float* b2  = (const float*)d_in[6];
    const float* f1w = (const float*)d_in[7];
    const float* f1b = (const float*)d_in[8];
    const float* f2w = (const float*)d_in[9];
    const float* f2b = (const float*)d_in[10];
    float* out = (float*)d_out;

    deg_count_kernel<<<(N_EDGES + 255) / 256, 256>>>(ei, batch);
    scan_one<<<N_SCANBLK, SCAN_B>>>();
    fill_kernel<<<(N_EDGES + 255) / 256, 256>>>(ei, x);

    gemm1_fused<<<(N_NODES + 31) / 32, 256>>>(W1, b1);
    agg2_kernel<<<(N_NODES * 32 + 255) / 256, 256>>>();
    {
        dim3 grid((N_NODES + GM - 1) / GM, 256 / GN);
        gemm2_tc<<<grid, 256>>>(W2, b2, batch);
    }
    head_kernel<<<N_GRAPHS, 128>>>(f1w, f1b, f2w, f2b, out);
}

// round 15
// speedup vs baseline: 1.0107x; 1.0107x over previous
#include <cuda_runtime.h>
#include <cuda_bf16.h>
#include <math.h>

#define N_NODES 50000
#define N_EDGES 800000
#define N_GRAPHS 256
#define D_HID 256
#define SCAN_B 1024
#define N_SCANBLK ((N_NODES + SCAN_B - 1) / SCAN_B)   // 49

// ---------------- scratch (device globals; all self-restoring) ---------------
__device__ float g_dinv[N_NODES];
__device__ int   g_deg[N_NODES];                       // restored by scan_one
__device__ int   g_rowptr[N_NODES + 1];
__device__ int   g_cursor[N_NODES];
__device__ int   g_colidx[N_EDGES];
__device__ unsigned long long g_scanstate[N_SCANBLK];  // restored by fill
__device__ int   g_ticket;                             // restored by fill
__device__ float g_xs[(size_t)N_NODES * 16];           // dinv[n]*x[n], padded to 16
__device__ __nv_bfloat16 g_h1[(size_t)N_NODES * D_HID];
__device__ __nv_bfloat16 g_agg[(size_t)N_NODES * D_HID];
__device__ float g_pool[N_GRAPHS * D_HID];             // restored by head
__device__ int   g_cnt[N_GRAPHS];                      // restored by head
__device__ int   g_is32_ei;
__device__ int   g_is32_batch;

// fast selu: __expf (MUFU.EX2) — rel err ~1e-6 on the negative branch,
// 3 orders below the tf32/bf16 error already carried (4.2e-5)
__device__ __forceinline__ float selu_f(float v) {
    const float a = 1.6732632423543772f, s = 1.0507009873554805f;
    return v > 0.f ? s * v : s * a * (__expf(v) - 1.f);
}

__device__ __forceinline__ int load_idx(const void* p, long long i, int is32) {
    if (is32) return ((const int*)p)[i];
    return (int)((const long long*)p)[i];
}

__device__ __forceinline__ unsigned f2tf32(float f) {
    unsigned r;
    asm("cvt.rna.tf32.f32 %0, %1;" : "=r"(r) : "f"(f));
    return r;
}

// ------ deg/cnt histograms with per-block dtype sniff (no init kernel) -------
__global__ void deg_count_kernel(const void* __restrict__ ei, const void* __restrict__ batch) {
    __shared__ int s_ei, s_b;
    int t = threadIdx.x;
    if (t < 32) {
        int v = ((const int*)ei)[2 * (t * 256) + 1];
        unsigned m = __ballot_sync(0xffffffffu, v != 0);
        int w = ((const int*)batch)[2 * (t * 256) + 1];
        unsigned m2 = __ballot_sync(0xffffffffu, w != 0);
        if (t == 0) { s_ei = (m != 0); s_b = (m2 != 0); }
    }
    __syncthreads();
    int is32e = s_ei, is32b = s_b;
    int i = blockIdx.x * blockDim.x + t;
    if (i == 0) { g_is32_ei = is32e; g_is32_batch = is32b; }
    if (i < N_EDGES) atomicAdd(&g_deg[load_idx(ei, (long long)N_EDGES + i, is32e)], 1);
    if (i < N_NODES) atomicAdd(&g_cnt[load_idx(batch, i, is32b)], 1);
}

// ------- single-kernel decoupled-lookback scan (+cursor+dinv, deg restore) ---
__global__ void __launch_bounds__(SCAN_B) scan_one() {
    __shared__ int warp_sums[32];
    __shared__ int s_bid, s_exc;
    int t = threadIdx.x;
    if (t == 0) s_bid = atomicAdd(&g_ticket, 1);
    __syncthreads();
    int b = s_bid;
    int i = b * SCAN_B + t;
    int v = (i < N_NODES) ? g_deg[i] : 0;
    int x = v;
    #pragma unroll
    for (int off = 1; off < 32; off <<= 1) {
        int y = __shfl_up_sync(0xffffffffu, x, off);
        if ((t & 31) >= off) x += y;
    }
    if ((t & 31) == 31) warp_sums[t >> 5] = x;
    __syncthreads();
    if (t < 32) {
        int s = warp_sums[t];
        #pragma unroll
        for (int off = 1; off < 32; off <<= 1) {
            int y = __shfl_up_sync(0xffffffffu, s, off);
            if (t >= off) s += y;
        }
        warp_sums[t] = s;
    }
    __syncthreads();
    int inc = x + ((t >= 32) ? warp_sums[(t >> 5) - 1] : 0);

    if (t == 0) {
        int total = warp_sums[31];
        if (b == 0) {
            atomicExch(&g_scanstate[0], (2ULL << 32) | (unsigned)total);
            s_exc = 0;
        } else {
            atomicExch(&g_scanstate[b], (1ULL << 32) | (unsigned)total);
            int exc = 0;
            int j = b - 1;
            while (true) {
                unsigned long long st;
                do { st = atomicAdd(&g_scanstate[j], 0ULL); } while ((st >> 32) == 0ULL);
                exc += (int)(unsigned)st;
                if ((st >> 32) == 2ULL) break;
                j--;
            }
            atomicExch(&g_scanstate[b], (2ULL << 32) | (unsigned)(total + exc));
            s_exc = exc;
        }
    }
    __syncthreads();
    int exc = s_exc;
    int r = exc + inc - v;   // exclusive prefix
    if (i < N_NODES) {
        g_rowptr[i] = r;
        g_cursor[i] = r;
        g_dinv[i] = rsqrtf((float)(v + 1));
        g_deg[i] = 0;                       // restore for next run
    }
    if (i == N_NODES - 1) g_rowptr[N_NODES] = exc + inc;
}

// fill colidx + xs precompute (dinv ready) + scan-state restore
__global__ void fill_kernel(const void* __restrict__ ei, const float* __restrict__ x) {
    int i = blockIdx.x * blockDim.x + threadIdx.x;
    int is32 = g_is32_ei;
    if (i < N_EDGES) {
        int d = load_idx(ei, (long long)N_EDGES + i, is32);
        int p = atomicAdd(&g_cursor[d], 1);
        g_colidx[p] = load_idx(ei, i, is32);
    }
    if (i < N_NODES) {
        float di = g_dinv[i];
        const float* xr = x + (size_t)i * 14;
        float4* o = (float4*)(g_xs + (size_t)i * 16);
        o[0] = make_float4(di * xr[0],  di * xr[1],  di * xr[2],  di * xr[3]);
        o[1] = make_float4(di * xr[4],  di * xr[5],  di * xr[6],  di * xr[7]);
        o[2] = make_float4(di * xr[8],  di * xr[9],  di * xr[10], di * xr[11]);
        o[3] = make_float4(di * xr[12], di * xr[13], 0.f, 0.f);
    }
    if (i < N_SCANBLK) g_scanstate[i] = 0ULL;   // restore (scan_one fully done)
    if (i == N_SCANBLK) g_ticket = 0;           // restore
}

// ------- layer 1 fused: float4 gather of xs (8 edges/iter/warp), then GEMM ---
__global__ void gemm1_fused(const float* __restrict__ W1, const float* __restrict__ b1) {
    __shared__ __align__(16) float sx[32][16];
    int row0 = blockIdx.x * 32;
    int tid = threadIdx.x;  // 256
    int warp = tid >> 5, lane = tid & 31;
    int slot = lane >> 2;   // 0..7 edge slot
    int q = lane & 3;       // quad within xs row
    const float4* xs4 = (const float4*)g_xs;

    // phase 1: each warp aggregates 4 rows; all 32 lanes active
    #pragma unroll
    for (int rr = 0; rr < 4; rr++) {
        int r = warp * 4 + rr;
        int row = row0 + r;
        float4 acc = make_float4(0.f, 0.f, 0.f, 0.f);
        float di = 0.f;
        if (row < N_NODES) {
            di = g_dinv[row];
            if (slot == 0) acc = xs4[(size_t)row * 4 + q];   // self term
            int e0 = g_rowptr[row], e1 = g_rowptr[row + 1];
            int deg = e1 - e0;
            int nfull = deg >> 3;
            int e = e0 + slot;
            // full iterations: no bounds check
            for (int it = 0; it < nfull; it++, e += 8) {
                int s = g_colidx[e];
                float4 v = xs4[(size_t)s * 4 + q];
                acc.x += v.x; acc.y += v.y; acc.z += v.z; acc.w += v.w;
            }
            // single predicated tail
            if (e < e1) {
                int s = g_colidx[e];
                float4 v = xs4[(size_t)s * 4 + q];
                acc.x += v.x; acc.y += v.y; acc.z += v.z; acc.w += v.w;
            }
        }
        // reduce over the 8 slots (lane bits 2..4 -> xor offsets 4,8,16)
        #pragma unroll
        for (int off = 4; off < 32; off <<= 1) {
            acc.x += __shfl_xor_sync(0xffffffffu, acc.x, off);
            acc.y += __shfl_xor_sync(0xffffffffu, acc.y, off);
            acc.z += __shfl_xor_sync(0xffffffffu, acc.z, off);
            acc.w += __shfl_xor_sync(0xffffffffu, acc.w, off);
        }
        if (slot == 0) {
            float4 o = make_float4(di * acc.x, di * acc.y, di * acc.z, di * acc.w);
            *(float4*)&sx[r][q * 4] = o;
        }
    }
    __syncthreads();

    // phase 2: [32,14] @ [14,256] + bias + selu -> bf16 h1
    float w[14];
    #pragma unroll
    for (int k = 0; k < 14; k++) w[k] = W1[k * 256 + tid];
    float bj = b1[tid];
    for (int r = 0; r < 32; r++) {
        int row = row0 + r;
        if (row >= N_NODES) break;
        float acc = bj;
        #pragma unroll
        for (int k = 0; k < 14; k++) acc += sx[r][k] * w[k];
        g_h1[(size_t)row * 256 + tid] = __float2bfloat16(selu_f(acc));
    }
}

// ------- layer 2 aggregate: bf16 gather, unroll 8/4/1 ladder -----------------
__global__ void agg2_kernel() {
    int w = (blockIdx.x * blockDim.x + threadIdx.x) >> 5;
    int lane = threadIdx.x & 31;
    if (w >= N_NODES) return;
    float di = g_dinv[w];
    float acc[8];
    {
        float4 raw = ((const float4*)(g_h1 + (size_t)w * 256))[lane];
        const __nv_bfloat162* p = (const __nv_bfloat162*)&raw;
        #pragma unroll
        for (int q = 0; q < 4; q++) {
            float2 v = __bfloat1622float2(p[q]);
            acc[2 * q]     = di * v.x;
            acc[2 * q + 1] = di * v.y;
        }
    }
    int e0 = g_rowptr[w], e1 = g_rowptr[w + 1];
    int e = e0;
    for (; e + 8 <= e1; e += 8) {
        int s[8];
        float ds[8];
        float4 raw[8];
        #pragma unroll
        for (int u = 0; u < 8; u++) s[u] = g_colidx[e + u];
        #pragma unroll
        for (int u = 0; u < 8; u++) ds[u] = g_dinv[s[u]];
        #pragma unroll
        for (int u = 0; u < 8; u++)
            raw[u] = ((const float4*)(g_h1 + (size_t)s[u] * 256))[lane];
        #pragma unroll
        for (int u = 0; u < 8; u++) {
            const __nv_bfloat162* p = (const __nv_bfloat162*)&raw[u];
            #pragma unroll
            for (int q = 0; q < 4; q++) {
                float2 v = __bfloat1622float2(p[q]);
                acc[2 * q]     += ds[u] * v.x;
                acc[2 * q + 1] += ds[u] * v.y;
            }
        }
    }
    for (; e + 4 <= e1; e += 4) {
        int s[4];
        float ds[4];
        float4 raw[4];
        #pragma unroll
        for (int u = 0; u < 4; u++) s[u] = g_colidx[e + u];
        #pragma unroll
        for (int u = 0; u < 4; u++) ds[u] = g_dinv[s[u]];
        #pragma unroll
        for (int u = 0; u < 4; u++)
            raw[u] = ((const float4*)(g_h1 + (size_t)s[u] * 256))[lane];
        #pragma unroll
        for (int u = 0; u < 4; u++) {
            const __nv_bfloat162* p = (const __nv_bfloat162*)&raw[u];
            #pragma unroll
            for (int q = 0; q < 4; q++) {
                float2 v = __bfloat1622float2(p[q]);
                acc[2 * q]     += ds[u] * v.x;
                acc[2 * q + 1] += ds[u] * v.y;
            }
        }
    }
    for (; e < e1; e++) {
        int s = g_colidx[e];
        float ds = g_dinv[s];
        float4 raw = ((const float4*)(g_h1 + (size_t)s * 256))[lane];
        const __nv_bfloat162* p = (const __nv_bfloat162*)&raw;
        #pragma unroll
        for (int q = 0; q < 4; q++) {
            float2 v = __bfloat1622float2(p[q]);
            acc[2 * q]     += ds * v.x;
            acc[2 * q + 1] += ds * v.y;
        }
    }
    __nv_bfloat162 h[4];
    #pragma unroll
    for (int q = 0; q < 4; q++)
        h[q] = __floats2bfloat162_rn(di * acc[2 * q], di * acc[2 * q + 1]);
    ((float4*)(g_agg + (size_t)w * 256))[lane] = *(float4*)h;
}

// ---------------- GEMM2 (tf32 TC, bf16 A) with fused bias+selu+pool ----------
#define GM 128
#define GN 128
#define GK 32
#define GS (GM + 4)

__global__ void __launch_bounds__(256, 2) gemm2_tc(const float* __restrict__ W,
                                                   const float* __restrict__ bias,
                                                   const void* __restrict__ batch) {
    __shared__ unsigned As[GK][GS];
    __shared__ unsigned Bs[GK][GS];
    int m0 = blockIdx.x * GM, n0 = blockIdx.y * GN;
    int tid = threadIdx.x;
    int lane = tid & 31, warp = tid >> 5;
    int wm = (warp >> 1) * 32;
    int wn = (warp & 1) * 64;
    int g = lane >> 2, tg = lane & 3;

    float d[2][8][4];
    #pragma unroll
    for (int mi = 0; mi < 2; mi++)
        #pragma unroll
        for (int ni = 0; ni < 8; ni++)
            #pragma unroll
            for (int q = 0; q < 4; q++) d[mi][ni][q] = 0.f;

    for (int k0 = 0; k0 < 256; k0 += GK) {
        #pragma unroll
        for (int it = 0; it < 2; it++) {
            int idx = tid + it * 256;
            int row = idx >> 2;
            int c = (idx & 3) * 8;
            float4 raw = make_float4(0.f, 0.f, 0.f, 0.f);
            if (m0 + row < N_NODES)
                raw = *(const float4*)(g_agg + (size_t)(m0 + row) * 256 + k0 + c);
            const __nv_bfloat162* p = (const __nv_bfloat162*)&raw;
            #pragma unroll
            for (int q = 0; q < 4; q++) {
                float2 v = __bfloat1622float2(p[q]);
                As[c + 2 * q][row]     = f2tf32(v.x);
                As[c + 2 * q + 1][row] = f2tf32(v.y);
            }
        }
        #pragma unroll
        for (int it = 0; it < 4; it++) {
            int idx = tid + it * 256;
            int kr = idx >> 5;
            int nc = (idx & 31) * 4;
            float4 bv = *(const float4*)(W + (size_t)(k0 + kr) * 256 + n0 + nc);
            Bs[kr][nc + 0] = f2tf32(bv.x);
            Bs[kr][nc + 1] = f2tf32(bv.y);
            Bs[kr][nc + 2] = f2tf32(bv.z);
            Bs[kr][nc + 3] = f2tf32(bv.w);
        }
        __syncthreads();

        #pragma unroll
        for (int kk = 0; kk < GK; kk += 8) {
            unsigned a[2][4], b[8][2];
            #pragma unroll
            for (int mi = 0; mi < 2; mi++) {
                int mb = wm + mi * 16;
                a[mi][0] = As[kk + tg][mb + g];
                a[mi][1] = As[kk + tg][mb + g + 8];
                a[mi][2] = As[kk + tg + 4][mb + g];
                a[mi][3] = As[kk + tg + 4][mb + g + 8];
            }
            #pragma unroll
            for (int ni = 0; ni < 8; ni++) {
                int nb = wn + ni * 8;
                b[ni][0] = Bs[kk + tg][nb + g];
                b[ni][1] = Bs[kk + tg + 4][nb + g];
            }
            #pragma unroll
            for (int mi = 0; mi < 2; mi++)
                #pragma unroll
                for (int ni = 0; ni < 8; ni++)
                    asm volatile(
                        "mma.sync.aligned.m16n8k8.row.col.f32.tf32.tf32.f32 "
                        "{%0,%1,%2,%3},{%4,%5,%6,%7},{%8,%9},{%0,%1,%2,%3};"
                        : "+f"(d[mi][ni][0]), "+f"(d[mi][ni][1]),
                          "+f"(d[mi][ni][2]), "+f"(d[mi][ni][3])
                        : "r"(a[mi][0]), "r"(a[mi][1]), "r"(a[mi][2]), "r"(a[mi][3]),
                          "r"(b[ni][0]), "r"(b[ni][1]));
        }
        __syncthreads();
    }

    // ---- fused epilogue: bias + selu + segmented pool -> g_pool atomics ----
    int is32 = g_is32_batch;
    #pragma unroll
    for (int mi = 0; mi < 2; mi++) {
        int rbase = m0 + wm + mi * 16;
        int r0 = rbase + g;
        int r1 = r0 + 8;
        bool full = (rbase + 15) < N_NODES;
        int gid_first = load_idx(batch, full ? rbase : (N_NODES - 1), is32);
        int gid_last  = load_idx(batch, full ? (rbase + 15) : (N_NODES - 1), is32);
        bool uniform = full && (gid_first == gid_last);
        #pragma unroll
        for (int ni = 0; ni < 8; ni++) {
            int c0 = n0 + wn + ni * 8 + 2 * tg;
            float bz0 = bias[c0], bz1 = bias[c0 + 1];
            float v00 = selu_f(d[mi][ni][0] + bz0);
            float v01 = selu_f(d[mi][ni][1] + bz1);
            float v10 = selu_f(d[mi][ni][2] + bz0);
            float v11 = selu_f(d[mi][ni][3] + bz1);
            if (uniform) {
                float s0 = v00 + v10;
                float s1 = v01 + v11;
                #pragma unroll
                for (int off = 4; off < 32; off <<= 1) {
                    s0 += __shfl_xor_sync(0xffffffffu, s0, off);
                    s1 += __shfl_xor_sync(0xffffffffu, s1, off);
                }
                if (g == 0) {
                    atomicAdd(&g_pool[gid_first * 256 + c0], s0);
                    atomicAdd(&g_pool[gid_first * 256 + c0 + 1], s1);
                }
            } else {
                if (r0 < N_NODES) {
                    int gr = load_idx(batch, r0, is32);
                    atomicAdd(&g_pool[gr * 256 + c0], v00);
                    atomicAdd(&g_pool[gr * 256 + c0 + 1], v01);
                }
                if (r1 < N_NODES) {
                    int gr = load_idx(batch, r1, is32);
                    atomicAdd(&g_pool[gr * 256 + c0], v10);
                    atomicAdd(&g_pool[gr * 256 + c0 + 1], v11);
                }
            }
        }
    }
}

// ---------------- head (restores g_pool/g_cnt to zero) -----------------------
__global__ void head_kernel(const float* __restrict__ fc1w, const float* __restrict__ fc1b,
                            const float* __restrict__ fc2w, const float* __restrict__ fc2b,
                            float* __restrict__ out) {
    __shared__ __align__(16) float sp[256];
    __shared__ __align__(16) float sg[128];
    __shared__ float slog[2];
    int g = blockIdx.x, t = threadIdx.x;  // 128 threads
    float c = fmaxf((float)g_cnt[g], 1.0f);
    for (int j = t; j < 256; j += 128) {
        sp[j] = selu_f(g_pool[g * 256 + j] / c);
        g_pool[g * 256 + j] = 0.f;     // restore for next run
    }
    __syncthreads();
    if (t == 0) g_cnt[g] = 0;          // restore (after c read)
    float acc = fc1b[t];
    for (int k = 0; k < 256; k++) acc += sp[k] * fc1w[k * 128 + t];
    sg[t] = selu_f(acc);
    __syncthreads();
    if (t < 2) {
        float a = fc2b[t];
        for (int k = 0; k < 128; k++) a += sg[k] * fc2w[k * 2 + t];
        slog[t] = a;
    }
    __syncthreads();
    if (t < 2) {
        float m = fmaxf(slog[0], slog[1]);
        float lse = m + logf(expf(slog[0] - m) + expf(slog[1] - m));
        out[g * 2 + t] = slog[t] - lse;
    }
}

// ---------------- launch -----------------------------------------------------
extern "C" void kernel_launch(void* const* d_in, const int* in_sizes, int n_in,
                              void* d_out, int out_size) {
    const float* x     = (const float*)d_in[0];
    const void*  ei    = d_in[1];
    const void*  batch = d_in[2];
    const float* W1  = (const float*)d_in[3];
    const float* b1  = (const float*)d_in[4];
    const float* W2  = (const float*)d_in[5];
    const float* b2  = (const float*)d_in[6];
    const float* f1w = (const float*)d_in[7];
    const float* f1b = (const float*)d_in[8];
    const float* f2w = (const float*)d_in[9];
    const float* f2b = (const float*)d_in[10];
    float* out = (float*)d_out;

    deg_count_kernel<<<(N_EDGES + 255) / 256, 256>>>(ei, batch);
    scan_one<<<N_SCANBLK, SCAN_B>>>();
    fill_kernel<<<(N_EDGES + 255) / 256, 256>>>(ei, x);

    gemm1_fused<<<(N_NODES + 31) / 32, 256>>>(W1, b1);
    agg2_kernel<<<(N_NODES * 32 + 255) / 256, 256>>>();
    {
        dim3 grid((N_NODES + GM - 1) / GM, 256 / GN);
        gemm2_tc<<<grid, 256>>>(W2, b2, batch);
    }
    head_kernel<<<N_GRAPHS, 128>>>(f1w, f1b, f2w, f2b, out);
}